// round 17
// baseline (speedup 1.0000x reference)
#include <cuda_runtime.h>
#include <math.h>

#define NEGV (-1e30f)

// B=8, S=512, L=32, M=64
#define B_ 8
#define S_ 512
#define L_ 32
#define M_ 64
#define SP_ (S_ + 2)          // padded frames: prefetch never needs a frame bounds check
#define RW_ 68                // row stride: 64 paired slots + s0 + pad
#define LOG2E_ 1.4426950408889634f
#define LN2_   0.6931471805599453f

// scratch[b][e][cur][RW_]: slot 2p   = seg value for jm1 = p+1   (j = p+2)
//                          slot 2p+1 = seg value for jm1 = p+33  (j = p+34; p=31 -> invalid, 0)
//                          slot 64   = jm1 = 0 (s0).   All values *LOG2E (log2 domain).
__device__ float g_scratch[B_ * SP_ * L_ * RW_ + 16];

// slot of jm1=g (1..63) in the paired row
#define PSLOT(g) ((g) <= 32 ? 2 * ((g) - 1) : 2 * ((g) - 33) + 1)

__device__ __forceinline__ float ex2f(float x) {
    float y; asm("ex2.approx.ftz.f32 %0, %1;" : "=f"(y) : "f"(x)); return y;
}
__device__ __forceinline__ float lg2f(float x) {
    float y; asm("lg2.approx.ftz.f32 %0, %1;" : "=f"(y) : "f"(x)); return y;
}
__device__ __forceinline__ float redux_max_f32(float x) {      // exact keyed version (cold paths)
    unsigned u = __float_as_uint(x);
    unsigned k = u ^ (((unsigned)((int)u >> 31)) | 0x80000000u);
    unsigned r = __reduce_max_sync(0xffffffffu, k);
    return __uint_as_float(r ^ ((~((unsigned)((int)r >> 31))) | 0x80000000u));
}

// -------- pre-pass: gather band into paired [b][e][cur][RW_] layout, log2-scaled --------
__global__ void transpose_kernel(const float* __restrict__ seg) {
    int be = blockIdx.x;
    int b = be >> 9;
    int e = be & (S_ - 1);
    __shared__ float tile[L_][M_ + 1];
    int tid = threadIdx.x;
    for (int idx = tid; idx < M_ * L_; idx += 256) {
        int jm1 = idx >> 5;
        int c   = idx & 31;
        float v = 0.0f;
        int s = e - jm1;
        if (s >= 0) v = seg[(((size_t)b * S_ + s) * S_ + e) * L_ + c] * LOG2E_;
        tile[c][jm1] = v;
    }
    __syncthreads();
    float* out = &g_scratch[((size_t)(b * SP_ + e)) * (L_ * RW_)];
    for (int idx = tid; idx < L_ * 64; idx += 256) {
        int c = idx >> 6;
        int q = idx & 63;
        int p = q >> 1;
        int jm1 = (q & 1) ? (p + 33) : (p + 1);
        out[c * RW_ + q] = (jm1 <= 63) ? tile[c][jm1] : 0.0f;
    }
    for (int c = tid; c < L_; c += 256) out[c * RW_ + 64] = tile[c][0];
}

// -------- sequential recurrence: one CTA per batch, warp = cur label --------
// alpha: pair (m, s), s in [1,2]; beta: scalar log2 in warp-private ring [cur][frame&63].
// Max reductions via REDUX.S32 on truncated values (within 1.0 of exact; exp-sum bias sized for it).
__global__ __launch_bounds__(1024, 1) void crf_kernel(const float* __restrict__ trans,
                                                      float* __restrict__ out) {
    __shared__ float2 s_alpha[2][L_];
    __shared__ float  s_beta[L_ * M_];

    const int b    = blockIdx.x;
    const int tid  = threadIdx.x;
    const int cur  = tid >> 5;
    const int lane = tid & 31;
    const bool lane0  = (lane == 0);
    const bool lane31 = (lane == 31);

    const float treg22 = trans[lane * L_ + cur] * LOG2E_ + 22.0f;   // T[prev=lane][cur] + bias 22
    const float diag   = trans[cur * L_ + cur] * LOG2E_;
    const float* seg_base = &g_scratch[((size_t)(b * SP_)) * (L_ * RW_)];
    float* ring = &s_beta[cur * M_];

    for (int i = tid; i < L_ * M_; i += 1024) s_beta[i] = NEGV;
    if (tid < L_) s_alpha[0][tid] = make_float2(seg_base[(size_t)tid * RW_ + 64], 1.0f);

    const float fja = (float)(lane + 2), fjb = (float)(lane + 34);
    const float da  = diag * (float)(lane + 1);
    const float db  = diag * (float)(lane + 33);

    const float* row_lab = seg_base + (size_t)cur * RW_;

    // priming: s0 for frame 1; Rest[1] = init segment [0,1] (j=2, jm1=1 -> slot 0)
    float s0_f, RestL;
    {
        const float* r1 = row_lab + (size_t)1 * (L_ * RW_);
        s0_f  = r1[64];
        RestL = r1[0] * 2.0f + diag;
    }
    // bundle B = frame 2
    float2 svB; float s0B, niB;
    {
        const float* r2 = row_lab + (size_t)2 * (L_ * RW_);
        svB = *(const float2*)(r2 + 2 * lane);
        s0B = r2[64];
        niB = r2[PSLOT(2)];
    }
    float2 svA; float s0A, niA;     // filled by first step
    __syncthreads();

    const float* pref = row_lab + (size_t)3 * (L_ * RW_);   // frame F+2 at F=1

// uses bundle U (frame F+1), loads bundle L (frame F+2); s0_f = frame F's s0
#define STEP_BODY(F, PH1, SVU, S0U, NIU, SVL, S0L, NIL)                              \
    {                                                                                \
        SVL = *(const float2*)(pref + 2 * lane);                                     \
        S0L = pref[64];                                                              \
        NIL = 0.0f;                                                                  \
        if (PH1) { if ((F) + 2 < M_) NIL = pref[PSLOT((F) + 2)]; }                   \
        pref += L_ * RW_;                                                            \
                                                                                     \
        /* beta[F-1][cur] = LSE2_prev( alpha-pair + T ) */                           \
        float2 ap = s_alpha[((F) - 1) & 1][lane];                                    \
        float Bm = (float)__reduce_max_sync(0xffffffffu, (int)ap.x);                 \
        unsigned bu = (unsigned)(ap.y * ex2f(ap.x + treg22 - Bm));                   \
        unsigned bsum = __reduce_add_sync(0xffffffffu, bu);                          \
        float beta = (Bm - 22.0f) + lg2f((float)bsum);                               \
                                                                                     \
        /* alpha[F] pair = LSE(RestL, beta + s0); both scalar -> select-free */      \
        float t1 = beta + s0_f;                                                      \
        float Am = fmaxf(RestL, t1);                                                 \
        float As = 1.0f + ex2f(0.0f - fabsf(RestL - t1));                            \
                                                                                     \
        if (lane0) {                                                                 \
            s_alpha[(F) & 1][cur] = make_float2(Am, As);                             \
            ring[((F) - 1) & 63] = beta;                                             \
        }                                                                            \
        __syncwarp();                                                                \
                                                                                     \
        /* Rest[F+1]: j=2..64 (+ init at lane31 in phase 1); ring warp-private */    \
        int ia = ((F) - 1 - lane) & 63;                                              \
        float ta = ring[ia] + fmaf(SVU.x, fja, da);                                  \
        float tbeta = ring[ia ^ 32];                                                 \
        float tb;                                                                    \
        if (PH1) tb = lane31 ? fmaf(NIU, (float)((F) + 2), diag * (float)((F) + 1))  \
                             : tbeta + fmaf(SVU.y, fjb, db);                         \
        else     tb = lane31 ? NEGV : tbeta + fmaf(SVU.y, fjb, db);                  \
        int mi = __reduce_max_sync(0xffffffffu, max((int)ta, (int)tb));              \
        float m24 = (float)(mi - 24);                                                \
        unsigned ru = (unsigned)(ex2f(ta - m24) + ex2f(tb - m24));                   \
        unsigned rsum = __reduce_add_sync(0xffffffffu, ru);                          \
        RestL = m24 + lg2f((float)rsum);                                             \
                                                                                     \
        s0_f = S0U;                                                                  \
    }

    for (int f = 1; f <= 61; f += 2) {
        STEP_BODY(f,     true, svB, s0B, niB, svA, s0A, niA) __syncthreads();
        STEP_BODY(f + 1, true, svA, s0A, niA, svB, s0B, niB) __syncthreads();
    }
    for (int f = 63; f < 510; f += 2) {
        STEP_BODY(f,     false, svB, s0B, niB, svA, s0A, niA) __syncthreads();
        STEP_BODY(f + 1, false, svA, s0A, niA, svB, s0B, niB) __syncthreads();
    }
    STEP_BODY(511, false, svB, s0B, niB, svA, s0A, niA)
#undef STEP_BODY

    // ---- log_z = LN2 * LSE2_cur ( alpha[S-1] pair ) ----
    if (cur == 0) {
        float2 p = s_alpha[(S_ - 1) & 1][lane];
        float v = p.x + lg2f(p.y);
        float m = redux_max_f32(v);
        unsigned u = (unsigned)ex2f(v - m + 24.0f);
        unsigned s = __reduce_add_sync(0xffffffffu, u);
        if (lane == 0) out[b] = (m - 24.0f + lg2f((float)s)) * LN2_;
    }
}

extern "C" void kernel_launch(void* const* d_in, const int* in_sizes, int n_in,
                              void* d_out, int out_size) {
    const float* seg   = (const float*)d_in[0];
    const float* trans = (const float*)d_in[1];
    if (n_in >= 2 && in_sizes[0] == L_ * L_) {
        trans = (const float*)d_in[0];
        seg   = (const float*)d_in[1];
    }
    float* out = (float*)d_out;

    transpose_kernel<<<B_ * S_, 256>>>(seg);
    crf_kernel<<<B_, 1024>>>(trans, out);
}